// round 2
// baseline (speedup 1.0000x reference)
#include <cuda_runtime.h>
#include <cstdint>
#include <math.h>

// ---------------------------------------------------------------------------
// Swin-style block:
//  LN1 -> shift(-4,-4) -> 8x8 window partition (q from D=0, kv from D=1)
//  q/kv projections -> windowed MHA (8 heads, d=32, rel-pos bias + mask)
//  -> proj + residual(q_in) -> window reverse -> shift(+4,+4) -> +x[:,0]
//  -> LN2 -> MLP (C->4C gelu -> C) -> residual
// All fp32. Staged kernels with static __device__ scratch.
// ---------------------------------------------------------------------------

#define MROWS 131072          // B*nwin*N = 2*1024*64 tokens
#define HID   1024

__device__ float g_qin [(size_t)MROWS * 256];
__device__ float g_kvin[(size_t)MROWS * 256];
__device__ float g_q   [(size_t)MROWS * 256];
__device__ float g_kv  [(size_t)MROWS * 512];
__device__ float g_ao  [(size_t)MROWS * 256];
__device__ float g_po  [(size_t)MROWS * 256];
__device__ float g_x1  [(size_t)MROWS * 256];
__device__ float g_x1n [(size_t)MROWS * 256];
__device__ float g_h   [(size_t)MROWS * HID];

// ---------------------------------------------------------------------------
// K1: LayerNorm + shift + window partition. One warp per output row.
// warp id = d*131072 + (wi*64 + n);   d=0 -> q_in, d=1 -> kv_in
// ---------------------------------------------------------------------------
__global__ void ln_window_kernel(const float* __restrict__ x,
                                 const float* __restrict__ g,
                                 const float* __restrict__ b,
                                 float* __restrict__ qin,
                                 float* __restrict__ kvin)
{
    int warp = (blockIdx.x * blockDim.x + threadIdx.x) >> 5;
    int lane = threadIdx.x & 31;
    int d  = warp >> 17;
    int r  = warp & 131071;
    int wi = r >> 6, n = r & 63;
    int bb = wi >> 10, wl = wi & 1023;
    int wh = wl >> 5,  wc = wl & 31;
    int i  = n >> 3,   j  = n & 7;
    int hs = (wh * 8 + i + 4) & 255;   // roll(-4)
    int ws = (wc * 8 + j + 4) & 255;
    const float* src = x + ((((size_t)(bb * 2 + d) * 256 + hs) * 256 + ws) << 8);

    float v[8]; float s = 0.f;
#pragma unroll
    for (int k = 0; k < 8; k++) { v[k] = src[lane + k * 32]; s += v[k]; }
#pragma unroll
    for (int o = 16; o; o >>= 1) s += __shfl_xor_sync(0xffffffffu, s, o);
    float mean = s * (1.f / 256.f);
    float vs = 0.f;
#pragma unroll
    for (int k = 0; k < 8; k++) { float t = v[k] - mean; vs += t * t; }
#pragma unroll
    for (int o = 16; o; o >>= 1) vs += __shfl_xor_sync(0xffffffffu, vs, o);
    float rstd = rsqrtf(vs * (1.f / 256.f) + 1e-5f);

    float* dst = (d == 0 ? qin : kvin) + ((size_t)r << 8);
#pragma unroll
    for (int k = 0; k < 8; k++) {
        int c = lane + k * 32;
        dst[c] = (v[k] - mean) * rstd * g[c] + b[c];
    }
}

// ---------------------------------------------------------------------------
// Plain row LayerNorm (for LN2 on x1). One warp per row, 131072 rows.
// ---------------------------------------------------------------------------
__global__ void ln_rows_kernel(const float* __restrict__ in,
                               const float* __restrict__ g,
                               const float* __restrict__ b,
                               float* __restrict__ out)
{
    int warp = (blockIdx.x * blockDim.x + threadIdx.x) >> 5;
    int lane = threadIdx.x & 31;
    const float* src = in + ((size_t)warp << 8);
    float v[8]; float s = 0.f;
#pragma unroll
    for (int k = 0; k < 8; k++) { v[k] = src[lane + k * 32]; s += v[k]; }
#pragma unroll
    for (int o = 16; o; o >>= 1) s += __shfl_xor_sync(0xffffffffu, s, o);
    float mean = s * (1.f / 256.f);
    float vs = 0.f;
#pragma unroll
    for (int k = 0; k < 8; k++) { float t = v[k] - mean; vs += t * t; }
#pragma unroll
    for (int o = 16; o; o >>= 1) vs += __shfl_xor_sync(0xffffffffu, vs, o);
    float rstd = rsqrtf(vs * (1.f / 256.f) + 1e-5f);
    float* dst = out + ((size_t)warp << 8);
#pragma unroll
    for (int k = 0; k < 8; k++) {
        int c = lane + k * 32;
        dst[c] = (v[k] - mean) * rstd * g[c] + b[c];
    }
}

// ---------------------------------------------------------------------------
// Generic tiled SGEMM:  C[M,N] = (A[M,K] @ B[N,K]^T + bias) * alpha  (+res)(gelu)
// BM=BN=64, BK=16, 256 threads, 4x4 microtile per thread.
// flags: bit0 = exact gelu, bit1 = residual add (res, same layout as C)
// ---------------------------------------------------------------------------
__global__ void sgemm_kernel(const float* __restrict__ A,
                             const float* __restrict__ B,
                             const float* __restrict__ bias,
                             const float* __restrict__ res,
                             float* __restrict__ Cout,
                             int M, int N, int K, float alpha, int flags)
{
    __shared__ float As[16][65];
    __shared__ float Bs[16][68];   // row = 68 floats = 272B (16B aligned)

    int tid = threadIdx.x;
    int bm = blockIdx.y * 64, bn = blockIdx.x * 64;
    int lr = tid >> 2, lc = tid & 3;
    int ty = tid >> 4, tx = tid & 15;

    float acc[4][4] = {};
    const float* Ap = A + (size_t)(bm + lr) * K + lc * 4;
    const float* Bp = B + (size_t)(bn + lr) * K + lc * 4;

    for (int k0 = 0; k0 < K; k0 += 16) {
        float4 a4 = *(const float4*)(Ap + k0);
        float4 b4 = *(const float4*)(Bp + k0);
        __syncthreads();
        As[lc * 4 + 0][lr] = a4.x; As[lc * 4 + 1][lr] = a4.y;
        As[lc * 4 + 2][lr] = a4.z; As[lc * 4 + 3][lr] = a4.w;
        Bs[lc * 4 + 0][lr] = b4.x; Bs[lc * 4 + 1][lr] = b4.y;
        Bs[lc * 4 + 2][lr] = b4.z; Bs[lc * 4 + 3][lr] = b4.w;
        __syncthreads();
#pragma unroll
        for (int k = 0; k < 16; k++) {
            float4 rb = *(const float4*)&Bs[k][tx * 4];
            float ra0 = As[k][ty * 4 + 0];
            float ra1 = As[k][ty * 4 + 1];
            float ra2 = As[k][ty * 4 + 2];
            float ra3 = As[k][ty * 4 + 3];
            acc[0][0] += ra0 * rb.x; acc[0][1] += ra0 * rb.y;
            acc[0][2] += ra0 * rb.z; acc[0][3] += ra0 * rb.w;
            acc[1][0] += ra1 * rb.x; acc[1][1] += ra1 * rb.y;
            acc[1][2] += ra1 * rb.z; acc[1][3] += ra1 * rb.w;
            acc[2][0] += ra2 * rb.x; acc[2][1] += ra2 * rb.y;
            acc[2][2] += ra2 * rb.z; acc[2][3] += ra2 * rb.w;
            acc[3][0] += ra3 * rb.x; acc[3][1] += ra3 * rb.y;
            acc[3][2] += ra3 * rb.z; acc[3][3] += ra3 * rb.w;
        }
    }

#pragma unroll
    for (int i = 0; i < 4; i++) {
        int row = bm + ty * 4 + i;
#pragma unroll
        for (int j = 0; j < 4; j++) {
            int col = bn + tx * 4 + j;
            float v = (acc[i][j] + bias[col]) * alpha;
            if (flags & 1) v = 0.5f * v * (1.f + erff(v * 0.70710678118654752f));
            if (flags & 2) v += res[(size_t)row * N + col];
            Cout[(size_t)row * N + col] = v;
        }
    }
}

// ---------------------------------------------------------------------------
// K4: windowed attention. One block per (window, head): 2048*8 = 16384 blocks.
// S = q k^T + rel_bias + mask ; softmax rows ; O = S v
// ---------------------------------------------------------------------------
__global__ void attn_kernel(const float* __restrict__ Q,
                            const float* __restrict__ KV,
                            const float* __restrict__ bt,    // [225][8]
                            const float* __restrict__ mask,  // [1024][64][64]
                            float* __restrict__ AO)
{
    __shared__ float qs[64][33], ks[64][33], vsm[64][33];
    __shared__ float Ss[64][65];

    int blk = blockIdx.x;
    int wi = blk >> 3, head = blk & 7;
    int tid = threadIdx.x;
    size_t qbase  = (size_t)wi * 64 * 256 + head * 32;
    size_t kvbase = (size_t)wi * 64 * 512 + head * 32;

    for (int idx = tid; idx < 2048; idx += 256) {
        int n = idx >> 5, dd = idx & 31;
        qs[n][dd]  = Q [qbase  + (size_t)n * 256 + dd];
        ks[n][dd]  = KV[kvbase + (size_t)n * 512 + dd];
        vsm[n][dd] = KV[kvbase + (size_t)n * 512 + 256 + dd];
    }
    __syncthreads();

    // S = q k^T, 4x4 microtile per thread
    int n0 = (tid >> 4) * 4, m0 = (tid & 15) * 4;
    float acc[4][4] = {};
#pragma unroll
    for (int dd = 0; dd < 32; dd++) {
        float qa[4], kb[4];
#pragma unroll
        for (int i = 0; i < 4; i++) qa[i] = qs[n0 + i][dd];
#pragma unroll
        for (int j = 0; j < 4; j++) kb[j] = ks[m0 + j][dd];
#pragma unroll
        for (int i = 0; i < 4; i++)
#pragma unroll
            for (int j = 0; j < 4; j++) acc[i][j] += qa[i] * kb[j];
    }

    const float* mrow = mask + (size_t)(wi & 1023) * 4096;
#pragma unroll
    for (int i = 0; i < 4; i++) {
        int n = n0 + i; int i1 = n >> 3, j1 = n & 7;
#pragma unroll
        for (int j = 0; j < 4; j++) {
            int m = m0 + j; int i2 = m >> 3, j2 = m & 7;
            int ridx = (i1 - i2 + 7) * 15 + (j1 - j2 + 7);
            Ss[n][m] = acc[i][j] + bt[ridx * 8 + head] + mrow[n * 64 + m];
        }
    }
    __syncthreads();

    // softmax: 4 threads per row (lanes aligned within warp)
    int row = tid >> 2, q4 = tid & 3;
    float mx = -1e30f;
    for (int m = q4; m < 64; m += 4) mx = fmaxf(mx, Ss[row][m]);
    mx = fmaxf(mx, __shfl_xor_sync(0xffffffffu, mx, 1));
    mx = fmaxf(mx, __shfl_xor_sync(0xffffffffu, mx, 2));
    float sum = 0.f;
    for (int m = q4; m < 64; m += 4) {
        float e = __expf(Ss[row][m] - mx); Ss[row][m] = e; sum += e;
    }
    sum += __shfl_xor_sync(0xffffffffu, sum, 1);
    sum += __shfl_xor_sync(0xffffffffu, sum, 2);
    float inv = 1.f / sum;
    for (int m = q4; m < 64; m += 4) Ss[row][m] *= inv;
    __syncthreads();

    // O = S @ v : thread -> (row, 8 head-dims)
    int dg = q4 * 8;
    float o[8] = {};
    for (int m = 0; m < 64; m++) {
        float s = Ss[row][m];
#pragma unroll
        for (int i = 0; i < 8; i++) o[i] += s * vsm[m][dg + i];
    }
    float* dst = AO + (size_t)(wi * 64 + row) * 256 + head * 32 + dg;
#pragma unroll
    for (int i = 0; i < 8; i++) dst[i] = o[i];
}

// ---------------------------------------------------------------------------
// K6: window reverse + roll(+4,+4) + residual with x[:,0]. One warp per row.
// ---------------------------------------------------------------------------
__global__ void reverse_residual_kernel(const float* __restrict__ x,
                                        const float* __restrict__ po,
                                        float* __restrict__ x1)
{
    int warp = (blockIdx.x * blockDim.x + threadIdx.x) >> 5;
    int lane = threadIdx.x & 31;
    int bb = warp >> 16, hw = warp & 65535;
    int h = hw >> 8, w = hw & 255;
    int hp = (h - 4) & 255, wp = (w - 4) & 255;   // inverse of roll(+4)
    int wh = hp >> 3, i = hp & 7, wc = wp >> 3, j = wp & 7;
    int wi = bb * 1024 + wh * 32 + wc, n = i * 8 + j;
    const float* xs = x  + ((size_t)(bb * 2) * 65536 + hw) * 256;      // x[b,0,h,w,:]
    const float* ps = po + (size_t)(wi * 64 + n) * 256;
    float* dst = x1 + ((size_t)warp << 8);
#pragma unroll
    for (int k = 0; k < 8; k++) {
        int c = lane + k * 32;
        dst[c] = xs[c] + ps[c];
    }
}

// ---------------------------------------------------------------------------
extern "C" void kernel_launch(void* const* d_in, const int* in_sizes, int n_in,
                              void* d_out, int out_size)
{
    const float* x   = (const float*)d_in[0];
    const float* mask= (const float*)d_in[1];
    const float* g1  = (const float*)d_in[2];
    const float* b1  = (const float*)d_in[3];
    const float* qw  = (const float*)d_in[4];
    const float* qb  = (const float*)d_in[5];
    const float* kvw = (const float*)d_in[6];
    const float* kvb = (const float*)d_in[7];
    const float* pw  = (const float*)d_in[8];
    const float* pb  = (const float*)d_in[9];
    const float* bt  = (const float*)d_in[10];
    const float* g2  = (const float*)d_in[11];
    const float* b2  = (const float*)d_in[12];
    const float* w1  = (const float*)d_in[13];
    const float* bi1 = (const float*)d_in[14];
    const float* w2  = (const float*)d_in[15];
    const float* bi2 = (const float*)d_in[16];
    float* out = (float*)d_out;

    float *qin, *kvin, *q, *kv, *ao, *po, *x1, *x1n, *h;
    cudaGetSymbolAddress((void**)&qin,  g_qin);
    cudaGetSymbolAddress((void**)&kvin, g_kvin);
    cudaGetSymbolAddress((void**)&q,    g_q);
    cudaGetSymbolAddress((void**)&kv,   g_kv);
    cudaGetSymbolAddress((void**)&ao,   g_ao);
    cudaGetSymbolAddress((void**)&po,   g_po);
    cudaGetSymbolAddress((void**)&x1,   g_x1);
    cudaGetSymbolAddress((void**)&x1n,  g_x1n);
    cudaGetSymbolAddress((void**)&h,    g_h);

    // K1: LN1 + shift + window partition (both depth slices)
    ln_window_kernel<<<32768, 256>>>(x, g1, b1, qin, kvin);
    // K2: q = (q_in @ qw^T + qb) * d^-0.5
    sgemm_kernel<<<dim3(4, 2048), 256>>>(qin, qw, qb, nullptr, q,
                                         MROWS, 256, 256, 0.17677669529663687f, 0);
    // K3: kv = kv_in @ kvw^T + kvb
    sgemm_kernel<<<dim3(8, 2048), 256>>>(kvin, kvw, kvb, nullptr, kv,
                                         MROWS, 512, 256, 1.f, 0);
    // K4: windowed attention
    attn_kernel<<<16384, 256>>>(q, kv, bt, mask, ao);
    // K5: proj + residual(q_in)
    sgemm_kernel<<<dim3(4, 2048), 256>>>(ao, pw, pb, qin, po,
                                         MROWS, 256, 256, 1.f, 2);
    // K6: window reverse + roll + residual with x[:,0]
    reverse_residual_kernel<<<16384, 256>>>(x, po, x1);
    // K7: LN2
    ln_rows_kernel<<<16384, 256>>>(x1, g2, b2, x1n);
    // K8: MLP up + exact gelu
    sgemm_kernel<<<dim3(16, 2048), 256>>>(x1n, w1, bi1, nullptr, h,
                                          MROWS, HID, 256, 1.f, 1);
    // K9: MLP down + residual(x1) -> final output
    sgemm_kernel<<<dim3(4, 2048), 256>>>(h, w2, bi2, x1, out,
                                         MROWS, 256, HID, 1.f, 2);
}